// round 2
// baseline (speedup 1.0000x reference)
#include <cuda_runtime.h>

// Problem constants (fixed by dataset)
#define NROWS 8192
#define DDIM  256
#define BM    64          // query rows per CTA
#define BN    64          // key tile per iteration
#define EPSF  1e-6f

#define QS_STRIDE 260     // pad: 260%32==4 -> conflict-free A-frag loads
#define KS_STRIDE 264     // pad: 264%32==8 -> conflict-free B-frag loads in BOTH gemm roles
#define PS_STRIDE 68      // pad: 68%32==4

#define SMEM_FLOATS (BM*QS_STRIDE + BN*KS_STRIDE + BM*PS_STRIDE + 5*64 + 2*64 + 2*64)
#define SMEM_BYTES  (SMEM_FLOATS * 4)

__device__ float g_qn[NROWS];
__device__ float g_tinv[NROWS];

__device__ __forceinline__ float f2tf32f(float x) {
    unsigned r;
    asm("cvt.rna.tf32.f32 %0, %1;" : "=r"(r) : "f"(x));
    return __uint_as_float(r);
}

__device__ __forceinline__ void mma_tf32(float d[4],
    unsigned a0, unsigned a1, unsigned a2, unsigned a3,
    unsigned b0, unsigned b1) {
    asm volatile(
        "mma.sync.aligned.m16n8k8.row.col.f32.tf32.tf32.f32 "
        "{%0,%1,%2,%3}, {%4,%5,%6,%7}, {%8,%9}, {%0,%1,%2,%3};\n"
        : "+f"(d[0]), "+f"(d[1]), "+f"(d[2]), "+f"(d[3])
        : "r"(a0), "r"(a1), "r"(a2), "r"(a3), "r"(b0), "r"(b1));
}

// ---------------- kernel 0: row norms + 1/t ----------------
__global__ void qn_kernel(const float* __restrict__ q, const float* __restrict__ cp) {
    int row  = blockIdx.x * 8 + (threadIdx.x >> 5);
    int lane = threadIdx.x & 31;
    const float4* qr = (const float4*)(q + (size_t)row * DDIM);
    float s = 0.0f;
#pragma unroll
    for (int i = 0; i < 2; i++) {
        float4 v = qr[lane + i * 32];
        s += v.x * v.x + v.y * v.y + v.z * v.z + v.w * v.w;
    }
#pragma unroll
    for (int o = 16; o > 0; o >>= 1) s += __shfl_xor_sync(0xffffffffu, s, o);
    if (lane == 0) {
        float cc = fmaxf(*cp, EPSF);
        g_qn[row]   = s;
        g_tinv[row] = 1.0f / fmaxf(1.0f - cc * s, EPSF);
    }
}

// ---------------- main fused kernel ----------------
__device__ __forceinline__ float neg_dist(float s, float qni, float ti,
                                          float qnj, float tj,
                                          float two_c, float inv_sqrt_c) {
    float diff = fmaxf(qni + qnj - 2.0f * s, 0.0f);
    float arg  = fmaf(two_c * ti * tj, diff, 1.0f);
    arg = fmaxf(arg, 1.0f + EPSF) + EPSF;
    float x = arg - 1.0f;                              // exact (Sterbenz)
    float ac = __logf(arg + sqrtf(x * (arg + 1.0f))); // acosh, cancellation-free
    return -inv_sqrt_c * ac;
}

__global__ __launch_bounds__(256, 1)
void hyp_attn_kernel(const float* __restrict__ q, const float* __restrict__ cp,
                     float* __restrict__ out) {
    extern __shared__ float smem[];
    float* Qs      = smem;                         // [BM][QS_STRIDE]
    float* Ks      = Qs + BM * QS_STRIDE;          // [BN][KS_STRIDE]
    float* Ps      = Ks + BN * KS_STRIDE;          // [BM][PS_STRIDE]
    float* qncol   = Ps + BM * PS_STRIDE;          // [BN]
    float* tinvcol = qncol + BN;                   // [BN]
    float* m_s     = tinvcol + BN;                 // [BM]
    float* l_s     = m_s + BM;                     // [BM]
    float* alpha_s = l_s + BM;                     // [BM]
    float* wmax    = alpha_s + BM;                 // [2][BM]
    float* wsum    = wmax + 2 * BM;                // [2][BM]

    const int tid  = threadIdx.x;
    const int w    = tid >> 5;
    const int lane = tid & 31;
    const int g    = lane >> 2;     // groupID
    const int tg   = lane & 3;      // thread-in-group

    const float cc         = fmaxf(*cp, EPSF);
    const float two_c      = 2.0f * cc;
    const float inv_sqrt_c = 1.0f / sqrtf(cc);

    const int rowbase = blockIdx.x * BM;

    // load Q tile once (tf32-rounded)
    {
        const float4* src = (const float4*)(q + (size_t)rowbase * DDIM);
#pragma unroll
        for (int i = 0; i < 16; i++) {
            int f  = tid + i * 256;
            int r  = f >> 6;
            int c4 = f & 63;
            float4 v = src[r * (DDIM / 4) + c4];
            float4 wv = make_float4(f2tf32f(v.x), f2tf32f(v.y), f2tf32f(v.z), f2tf32f(v.w));
            *(float4*)(Qs + r * QS_STRIDE + c4 * 4) = wv;
        }
    }
    if (tid < BM) { m_s[tid] = __int_as_float(0xff800000); l_s[tid] = 0.0f; }

    // GEMM1 warp coords: 4 (m) x 2 (n); warp tile 16x32 of S
    const int wm = w >> 1;
    const int wn = w & 1;
    const int lr0 = wm * 16 + g;      // local S row 0
    const int lr1 = lr0 + 8;          // local S row 1
    const float qni0 = g_qn[rowbase + lr0];
    const float qni1 = g_qn[rowbase + lr1];
    const float ti0  = g_tinv[rowbase + lr0];
    const float ti1  = g_tinv[rowbase + lr1];

    // GEMM2 warp coords: 2 (m) x 4 (n); warp tile 32x64 of O
    const int wm2 = w & 1;
    const int wn2 = w >> 1;
    const int r2  = wm2 * 32 + g;     // O local rows r2, r2+8, r2+16, r2+24

    float of[2][8][4];
#pragma unroll
    for (int mt = 0; mt < 2; mt++)
#pragma unroll
        for (int nt = 0; nt < 8; nt++)
#pragma unroll
            for (int e = 0; e < 4; e++) of[mt][nt][e] = 0.0f;

    for (int jt = 0; jt < NROWS / BN; jt++) {
        const int jbase = jt * BN;

        // ---- load K(=V) tile + column stats ----
        {
            const float4* ksrc = (const float4*)(q + (size_t)jbase * DDIM);
#pragma unroll
            for (int i = 0; i < 16; i++) {
                int f  = tid + i * 256;
                int r  = f >> 6;
                int c4 = f & 63;
                float4 v = ksrc[r * (DDIM / 4) + c4];
                float4 wv = make_float4(f2tf32f(v.x), f2tf32f(v.y), f2tf32f(v.z), f2tf32f(v.w));
                *(float4*)(Ks + r * KS_STRIDE + c4 * 4) = wv;
            }
            if (tid < BN) {
                qncol[tid]   = g_qn[jbase + tid];
                tinvcol[tid] = g_tinv[jbase + tid];
            }
        }
        __syncthreads();   // B1

        // ---- GEMM1: S = Q . K^T  (warp tile 16x32) ----
        float sf[4][4];
#pragma unroll
        for (int nt = 0; nt < 4; nt++)
#pragma unroll
            for (int e = 0; e < 4; e++) sf[nt][e] = 0.0f;

        const float* Arow0 = Qs + lr0 * QS_STRIDE;
        const float* Arow1 = Qs + lr1 * QS_STRIDE;
#pragma unroll 8
        for (int kk = 0; kk < DDIM; kk += 8) {
            unsigned a0 = __float_as_uint(Arow0[kk + tg]);
            unsigned a1 = __float_as_uint(Arow1[kk + tg]);
            unsigned a2 = __float_as_uint(Arow0[kk + tg + 4]);
            unsigned a3 = __float_as_uint(Arow1[kk + tg + 4]);
#pragma unroll
            for (int nt = 0; nt < 4; nt++) {
                const float* Brow = Ks + (wn * 32 + nt * 8 + g) * KS_STRIDE + kk;
                unsigned b0 = __float_as_uint(Brow[tg]);
                unsigned b1 = __float_as_uint(Brow[tg + 4]);
                mma_tf32(sf[nt], a0, a1, a2, a3, b0, b1);
            }
        }

        // ---- elementwise hyperbolic transform + row max ----
        float rmax0 = __int_as_float(0xff800000);
        float rmax1 = rmax0;
        const int grow0 = rowbase + lr0;
        const int grow1 = rowbase + lr1;
#pragma unroll
        for (int nt = 0; nt < 4; nt++) {
            const int cbase = wn * 32 + nt * 8 + tg * 2;
#pragma unroll
            for (int cc2 = 0; cc2 < 2; cc2++) {
                const int c   = cbase + cc2;
                const float qnj = qncol[c];
                const float tj  = tinvcol[c];
                float nd0 = neg_dist(sf[nt][cc2],     qni0, ti0, qnj, tj, two_c, inv_sqrt_c);
                float nd1 = neg_dist(sf[nt][2 + cc2], qni1, ti1, qnj, tj, two_c, inv_sqrt_c);
                if (jbase + c == grow0) nd0 = 0.0f;   // exact diagonal
                if (jbase + c == grow1) nd1 = 0.0f;
                sf[nt][cc2]     = nd0;
                sf[nt][2 + cc2] = nd1;
                rmax0 = fmaxf(rmax0, nd0);
                rmax1 = fmaxf(rmax1, nd1);
            }
        }
        rmax0 = fmaxf(rmax0, __shfl_xor_sync(0xffffffffu, rmax0, 1));
        rmax0 = fmaxf(rmax0, __shfl_xor_sync(0xffffffffu, rmax0, 2));
        rmax1 = fmaxf(rmax1, __shfl_xor_sync(0xffffffffu, rmax1, 1));
        rmax1 = fmaxf(rmax1, __shfl_xor_sync(0xffffffffu, rmax1, 2));
        if (tg == 0) { wmax[wn * BM + lr0] = rmax0; wmax[wn * BM + lr1] = rmax1; }
        __syncthreads();   // B2

        // ---- P = exp(nd - m_new), row sums, write P to smem ----
        const float mo0 = m_s[lr0], mo1 = m_s[lr1];
        const float mn0 = fmaxf(mo0, fmaxf(wmax[lr0], wmax[BM + lr0]));
        const float mn1 = fmaxf(mo1, fmaxf(wmax[lr1], wmax[BM + lr1]));
        float rsum0 = 0.0f, rsum1 = 0.0f;
#pragma unroll
        for (int nt = 0; nt < 4; nt++) {
            const int cbase = wn * 32 + nt * 8 + tg * 2;
            float p00 = __expf(sf[nt][0] - mn0);
            float p01 = __expf(sf[nt][1] - mn0);
            float p10 = __expf(sf[nt][2] - mn1);
            float p11 = __expf(sf[nt][3] - mn1);
            rsum0 += p00 + p01;
            rsum1 += p10 + p11;
            *(float2*)(Ps + lr0 * PS_STRIDE + cbase) =
                make_float2(f2tf32f(p00), f2tf32f(p01));
            *(float2*)(Ps + lr1 * PS_STRIDE + cbase) =
                make_float2(f2tf32f(p10), f2tf32f(p11));
        }
        rsum0 += __shfl_xor_sync(0xffffffffu, rsum0, 1);
        rsum0 += __shfl_xor_sync(0xffffffffu, rsum0, 2);
        rsum1 += __shfl_xor_sync(0xffffffffu, rsum1, 1);
        rsum1 += __shfl_xor_sync(0xffffffffu, rsum1, 2);
        if (tg == 0) { wsum[wn * BM + lr0] = rsum0; wsum[wn * BM + lr1] = rsum1; }
        __syncthreads();   // B3

        // ---- update running stats (one thread per row) ----
        if (tid < BM) {
            float mo = m_s[tid];
            float mn = fmaxf(mo, fmaxf(wmax[tid], wmax[BM + tid]));
            float al = __expf(mo - mn);
            l_s[tid]     = l_s[tid] * al + wsum[tid] + wsum[BM + tid];
            m_s[tid]     = mn;
            alpha_s[tid] = al;
        }
        __syncthreads();   // B4

        // ---- GEMM2: O = O*alpha + P . V  (warp tile 32x64) ----
        {
            const float al0 = alpha_s[r2];
            const float al1 = alpha_s[r2 + 8];
            const float al2 = alpha_s[r2 + 16];
            const float al3 = alpha_s[r2 + 24];
#pragma unroll
            for (int nt = 0; nt < 8; nt++) {
                of[0][nt][0] *= al0; of[0][nt][1] *= al0;
                of[0][nt][2] *= al1; of[0][nt][3] *= al1;
                of[1][nt][0] *= al2; of[1][nt][1] *= al2;
                of[1][nt][2] *= al3; of[1][nt][3] *= al3;
            }
#pragma unroll
            for (int kk = 0; kk < BN; kk += 8) {
                unsigned a[2][4];
#pragma unroll
                for (int mt = 0; mt < 2; mt++) {
                    const float* Pr0 = Ps + (wm2 * 32 + mt * 16 + g) * PS_STRIDE + kk;
                    const float* Pr1 = Pr0 + 8 * PS_STRIDE;
                    a[mt][0] = __float_as_uint(Pr0[tg]);
                    a[mt][1] = __float_as_uint(Pr1[tg]);
                    a[mt][2] = __float_as_uint(Pr0[tg + 4]);
                    a[mt][3] = __float_as_uint(Pr1[tg + 4]);
                }
#pragma unroll
                for (int nt = 0; nt < 8; nt++) {
                    const float* Bp = Ks + (kk + tg) * KS_STRIDE + wn2 * 64 + nt * 8 + g;
                    unsigned b0 = __float_as_uint(Bp[0]);
                    unsigned b1 = __float_as_uint(Bp[4 * KS_STRIDE]);
                    mma_tf32(of[0][nt], a[0][0], a[0][1], a[0][2], a[0][3], b0, b1);
                    mma_tf32(of[1][nt], a[1][0], a[1][1], a[1][2], a[1][3], b0, b1);
                }
            }
        }
        __syncthreads();   // B5 (protect Ks/Ps/stats before next iteration)
    }

    // ---- epilogue: O / l ----
    {
        const float li0 = 1.0f / l_s[r2];
        const float li1 = 1.0f / l_s[r2 + 8];
        const float li2 = 1.0f / l_s[r2 + 16];
        const float li3 = 1.0f / l_s[r2 + 24];
#pragma unroll
        for (int mt = 0; mt < 2; mt++) {
            const float liA = mt ? li2 : li0;
            const float liB = mt ? li3 : li1;
            const int grA = rowbase + wm2 * 32 + mt * 16 + g;
#pragma unroll
            for (int nt = 0; nt < 8; nt++) {
                const int col = wn2 * 64 + nt * 8 + tg * 2;
                *(float2*)(out + (size_t)grA * DDIM + col) =
                    make_float2(of[mt][nt][0] * liA, of[mt][nt][1] * liA);
                *(float2*)(out + (size_t)(grA + 8) * DDIM + col) =
                    make_float2(of[mt][nt][2] * liB, of[mt][nt][3] * liB);
            }
        }
    }
}

extern "C" void kernel_launch(void* const* d_in, const int* in_sizes, int n_in,
                              void* d_out, int out_size) {
    const float* q  = (const float*)d_in[0];
    const float* cp = (const float*)d_in[1];
    float* out      = (float*)d_out;

    // idempotent; first (non-captured) correctness call makes it stick
    cudaFuncSetAttribute(hyp_attn_kernel,
                         cudaFuncAttributeMaxDynamicSharedMemorySize, SMEM_BYTES);

    qn_kernel<<<NROWS / 8, 256>>>(q, cp);
    hyp_attn_kernel<<<NROWS / BM, 256, SMEM_BYTES>>>(q, cp, out);
}

// round 4
// speedup vs baseline: 1.2253x; 1.2253x over previous
#include <cuda_runtime.h>
#include <cstdint>

#define NROWS 8192
#define DDIM  256
#define BM    64
#define BN    64
#define NITER (NROWS/BN)
#define EPSF  1e-6f

#define QS_STRIDE 260
#define PS_STRIDE 68

#define QS_FLOATS (BM*QS_STRIDE)   // 16640
#define KS_FLOATS (BN*DDIM)        // 16384 per buffer (swizzled, no pad)
#define PS_FLOATS (BM*PS_STRIDE)   // 4352
#define SMEM_FLOATS (QS_FLOATS + 2*KS_FLOATS + PS_FLOATS + 2*BM)
#define SMEM_BYTES  (SMEM_FLOATS*4)

__device__ float  g_qtf[(size_t)NROWS*DDIM];  // tf32-rounded copy of q (8MB)
__device__ float2 g_qt[NROWS];                // (||q||^2, 1/t)

__device__ __forceinline__ float f2tf32f(float x) {
    unsigned r;
    asm("cvt.rna.tf32.f32 %0, %1;" : "=r"(r) : "f"(x));
    return __uint_as_float(r);
}

__device__ __forceinline__ float flg2(float x) {
    float r;
    asm("lg2.approx.f32 %0, %1;" : "=f"(r) : "f"(x));
    return r;
}

__device__ __forceinline__ float fex2(float x) {
    float r;
    asm("ex2.approx.f32 %0, %1;" : "=f"(r) : "f"(x));
    return r;
}

__device__ __forceinline__ void mma_tf32(float d[4],
    unsigned a0, unsigned a1, unsigned a2, unsigned a3,
    unsigned b0, unsigned b1) {
    asm volatile(
        "mma.sync.aligned.m16n8k8.row.col.f32.tf32.tf32.f32 "
        "{%0,%1,%2,%3}, {%4,%5,%6,%7}, {%8,%9}, {%0,%1,%2,%3};\n"
        : "+f"(d[0]), "+f"(d[1]), "+f"(d[2]), "+f"(d[3])
        : "r"(a0), "r"(a1), "r"(a2), "r"(a3), "r"(b0), "r"(b1));
}

// ---------------- prep: tf32 copy + row stats ----------------
__global__ void prep_kernel(const float* __restrict__ q, const float* __restrict__ cp) {
    int row  = blockIdx.x * 8 + (threadIdx.x >> 5);
    int lane = threadIdx.x & 31;
    const float4* qr = (const float4*)(q + (size_t)row * DDIM);
    float4* wr       = (float4*)(g_qtf + (size_t)row * DDIM);
    float s = 0.0f;
#pragma unroll
    for (int i = 0; i < 2; i++) {
        float4 v = qr[lane + i * 32];
        s += v.x * v.x + v.y * v.y + v.z * v.z + v.w * v.w;
        wr[lane + i * 32] = make_float4(f2tf32f(v.x), f2tf32f(v.y),
                                        f2tf32f(v.z), f2tf32f(v.w));
    }
#pragma unroll
    for (int o = 16; o > 0; o >>= 1) s += __shfl_xor_sync(0xffffffffu, s, o);
    if (lane == 0) {
        float cc = fmaxf(*cp, EPSF);
        g_qt[row] = make_float2(s, 1.0f / fmaxf(1.0f - cc * s, EPSF));
    }
}

// p = exp(-acosh(arg)/sqrt(c)) = 2^(-k*log2(y)),  y = arg + sqrt((arg-1)(arg+1))
__device__ __forceinline__ float pcalc(float s, float qni, float coef, float qnj, float kf) {
    float diff = fmaxf(qni + qnj - 2.0f * s, 0.0f);
    float arg  = fmaf(coef, diff, 1.0f);
    arg = fmaxf(arg, 1.0f + EPSF) + EPSF;
    float x = arg - 1.0f;
    float y = arg + sqrtf(x * (arg + 1.0f));
    return fex2(-kf * flg2(y));
}

__global__ __launch_bounds__(256, 1)
void hyp_attn_kernel(const float* __restrict__ cp, float* __restrict__ out) {
    extern __shared__ float smem[];
    float* Qs   = smem;                        // [BM][QS_STRIDE]
    float* Ks   = Qs + QS_FLOATS;              // 2 x [BN][256] swizzled
    float* Ps   = Ks + 2 * KS_FLOATS;          // [BM][PS_STRIDE]
    float* lred = Ps + PS_FLOATS;              // [2][BM]

    uint32_t smem_u32;
    asm("{ .reg .u64 t; cvta.to.shared.u64 t, %1; cvt.u32.u64 %0, t; }"
        : "=r"(smem_u32) : "l"(smem));
    const uint32_t ks_u32 = smem_u32 + QS_FLOATS * 4;

    const int tid  = threadIdx.x;
    const int w    = tid >> 5;
    const int lane = tid & 31;
    const int g    = lane >> 2;
    const int tg   = lane & 3;

    const float cc         = fmaxf(*cp, EPSF);
    const float two_c      = 2.0f * cc;
    const float kf         = 1.0f / sqrtf(cc);   // 1/sqrt(c)

    const int rowbase = blockIdx.x * BM;

    // GEMM1 warp coords: 4(m) x 2(n), warp tile 16x32 of S
    const int wm = w >> 1;
    const int wn = w & 1;
    const int lr0 = wm * 16 + g;
    const int lr1 = lr0 + 8;
    const float2 qt0 = g_qt[rowbase + lr0];
    const float2 qt1 = g_qt[rowbase + lr1];
    const float qni0 = qt0.x, qni1 = qt1.x;
    const float tc0  = two_c * qt0.y;   // 2c * ti0
    const float tc1  = two_c * qt1.y;
    const int grow0 = rowbase + lr0;
    const int grow1 = rowbase + lr1;

    // GEMM2 warp coords: 2(m) x 4(n), warp tile 32x64 of O
    const int wm2 = w & 1;
    const int wn2 = w >> 1;
    const int r2  = wm2 * 32 + g;

    // swizzle constants (GEMM1 B access: f(g) decomposition)
    const int g3h = (g & 3) << 3;
    const int g4  = g & 4;
    const int tA  = tg + g4;
    const int tB  = tg + (4 ^ g4);

    // ---- prologue: Q tile (already tf32) ----
    {
        const float4* src = (const float4*)(g_qtf + ((size_t)rowbase << 8));
#pragma unroll
        for (int i = 0; i < 16; i++) {
            int f  = tid + i * 256;
            int r  = f >> 6;
            int c4 = f & 63;
            *(float4*)(Qs + r * QS_STRIDE + c4 * 4) = src[(r << 6) + c4];
        }
    }

    // ---- prologue: issue cp.async for K(0) into buf0 ----
    {
        const float* src0 = g_qtf;   // jbase = 0
#pragma unroll
        for (int i = 0; i < 16; i++) {
            int f  = tid + i * 256;
            int r  = f >> 6;
            int c4 = f & 63;
            int csw = c4 ^ (((r & 3) << 1) | ((r >> 2) & 1));
            uint32_t dst = ks_u32 + (r << 10) + (csw << 4);
            asm volatile("cp.async.cg.shared.global [%0], [%1], 16;\n"
                         :: "r"(dst), "l"(src0 + (r << 8) + (c4 << 2)) : "memory");
        }
        asm volatile("cp.async.commit_group;\n" ::: "memory");
    }

    float of[2][8][4];
#pragma unroll
    for (int mt = 0; mt < 2; mt++)
#pragma unroll
        for (int nt = 0; nt < 8; nt++)
#pragma unroll
            for (int e = 0; e < 4; e++) of[mt][nt][e] = 0.0f;

    float rsum0 = 0.0f, rsum1 = 0.0f;

    for (int jt = 0; jt < NITER; jt++) {
        const int jbase = jt * BN;
        const float* Kb = Ks + (jt & 1) * KS_FLOATS;

        asm volatile("cp.async.wait_group 0;\n" ::: "memory");
        __syncthreads();   // B1: K(jt) visible; Ps free; GEMM2(jt-1) done

        // prefetch K(jt+1) into the other buffer (overlaps with this iter)
        if (jt + 1 < NITER) {
            const float* srcN = g_qtf + ((size_t)(jbase + BN) << 8);
            uint32_t base = ks_u32 + ((jt + 1) & 1) * (KS_FLOATS * 4);
#pragma unroll
            for (int i = 0; i < 16; i++) {
                int f  = tid + i * 256;
                int r  = f >> 6;
                int c4 = f & 63;
                int csw = c4 ^ (((r & 3) << 1) | ((r >> 2) & 1));
                uint32_t dst = base + (r << 10) + (csw << 4);
                asm volatile("cp.async.cg.shared.global [%0], [%1], 16;\n"
                             :: "r"(dst), "l"(srcN + (r << 8) + (c4 << 2)) : "memory");
            }
            asm volatile("cp.async.commit_group;\n" ::: "memory");
        }

        // ---- GEMM1: S = Q . K^T ----
        float sf[4][4];
#pragma unroll
        for (int nt = 0; nt < 4; nt++)
#pragma unroll
            for (int e = 0; e < 4; e++) sf[nt][e] = 0.0f;

        const float* A0 = Qs + lr0 * QS_STRIDE;
        const float* A1 = Qs + lr1 * QS_STRIDE;
        const float* Bp0 = Kb + ((wn * 32 +  0 + g) << 8);
        const float* Bp1 = Kb + ((wn * 32 +  8 + g) << 8);
        const float* Bp2 = Kb + ((wn * 32 + 16 + g) << 8);
        const float* Bp3 = Kb + ((wn * 32 + 24 + g) << 8);
#pragma unroll 8
        for (int kk = 0; kk < DDIM; kk += 8) {
            const int kx = kk ^ g3h;
            unsigned a0 = __float_as_uint(A0[kk + tg]);
            unsigned a1 = __float_as_uint(A1[kk + tg]);
            unsigned a2 = __float_as_uint(A0[kk + tg + 4]);
            unsigned a3 = __float_as_uint(A1[kk + tg + 4]);
            mma_tf32(sf[0], a0, a1, a2, a3,
                     __float_as_uint(Bp0[kx + tA]), __float_as_uint(Bp0[kx + tB]));
            mma_tf32(sf[1], a0, a1, a2, a3,
                     __float_as_uint(Bp1[kx + tA]), __float_as_uint(Bp1[kx + tB]));
            mma_tf32(sf[2], a0, a1, a2, a3,
                     __float_as_uint(Bp2[kx + tA]), __float_as_uint(Bp2[kx + tB]));
            mma_tf32(sf[3], a0, a1, a2, a3,
                     __float_as_uint(Bp3[kx + tA]), __float_as_uint(Bp3[kx + tB]));
        }

        // ---- transform: p = exp(-dist), accumulate l, store P (tf32) ----
#pragma unroll
        for (int nt = 0; nt < 4; nt++) {
            const int cbase = wn * 32 + nt * 8 + tg * 2;
            const int col0  = jbase + cbase;
            float4 qq = *(const float4*)((const float*)&g_qt[col0]);
            // qq = (qn_c, tinv_c, qn_c1, tinv_c1)
            float p00 = pcalc(sf[nt][0], qni0, tc0 * qq.y, qq.x, kf);
            float p01 = pcalc(sf[nt][1], qni0, tc0 * qq.w, qq.z, kf);
            float p10 = pcalc(sf[nt][2], qni1, tc1 * qq.y, qq.x, kf);
            float p11 = pcalc(sf[nt][3], qni1, tc1 * qq.w, qq.z, kf);
            if (col0     == grow0) p00 = 1.0f;   // exact diagonal
            if (col0 + 1 == grow0) p01 = 1.0f;
            if (col0     == grow1) p10 = 1.0f;
            if (col0 + 1 == grow1) p11 = 1.0f;
            rsum0 += p00 + p01;
            rsum1 += p10 + p11;
            *(float2*)(Ps + lr0 * PS_STRIDE + cbase) =
                make_float2(f2tf32f(p00), f2tf32f(p01));
            *(float2*)(Ps + lr1 * PS_STRIDE + cbase) =
                make_float2(f2tf32f(p10), f2tf32f(p11));
        }
        __syncthreads();   // B2: P visible

        // ---- GEMM2: O += P . V ----
#pragma unroll
        for (int kk = 0; kk < BN; kk += 8) {
            unsigned a[2][4];
#pragma unroll
            for (int mt = 0; mt < 2; mt++) {
                const float* Pr0 = Ps + (wm2 * 32 + mt * 16 + g) * PS_STRIDE + kk;
                const float* Pr1 = Pr0 + 8 * PS_STRIDE;
                a[mt][0] = __float_as_uint(Pr0[tg]);
                a[mt][1] = __float_as_uint(Pr1[tg]);
                a[mt][2] = __float_as_uint(Pr0[tg + 4]);
                a[mt][3] = __float_as_uint(Pr1[tg + 4]);
            }
            const float* V0 = Kb + ((kk + tg) << 8);
            const float* V1 = Kb + ((kk + tg + 4) << 8);
#pragma unroll
            for (int nt = 0; nt < 8; nt++) {
                const int cnt = ((wn2 << 6) + (nt << 3) + g) ^ (tg << 3);
                unsigned b0 = __float_as_uint(V0[cnt]);
                unsigned b1 = __float_as_uint(V1[cnt ^ 4]);
                mma_tf32(of[0][nt], a[0][0], a[0][1], a[0][2], a[0][3], b0, b1);
                mma_tf32(of[1][nt], a[1][0], a[1][1], a[1][2], a[1][3], b0, b1);
            }
        }
        // no end barrier needed: next iteration's B1 orders buffer reuse
    }

    // ---- reduce row sums ----
    rsum0 += __shfl_xor_sync(0xffffffffu, rsum0, 1);
    rsum0 += __shfl_xor_sync(0xffffffffu, rsum0, 2);
    rsum1 += __shfl_xor_sync(0xffffffffu, rsum1, 1);
    rsum1 += __shfl_xor_sync(0xffffffffu, rsum1, 2);
    if (tg == 0) { lred[wn * BM + lr0] = rsum0; lred[wn * BM + lr1] = rsum1; }
    __syncthreads();

    // ---- epilogue: O / l ----
    {
        const float li0 = 1.0f / (lred[r2]      + lred[BM + r2]);
        const float li1 = 1.0f / (lred[r2 + 8]  + lred[BM + r2 + 8]);
        const float li2 = 1.0f / (lred[r2 + 16] + lred[BM + r2 + 16]);
        const float li3 = 1.0f / (lred[r2 + 24] + lred[BM + r2 + 24]);
#pragma unroll
        for (int mt = 0; mt < 2; mt++) {
            const float liA = mt ? li2 : li0;
            const float liB = mt ? li3 : li1;
            const int grA = rowbase + wm2 * 32 + mt * 16 + g;
#pragma unroll
            for (int nt = 0; nt < 8; nt++) {
                const int col = wn2 * 64 + nt * 8 + tg * 2;
                *(float2*)(out + (size_t)grA * DDIM + col) =
                    make_float2(of[mt][nt][0] * liA, of[mt][nt][1] * liA);
                *(float2*)(out + (size_t)(grA + 8) * DDIM + col) =
                    make_float2(of[mt][nt][2] * liB, of[mt][nt][3] * liB);
            }
        }
    }
}

extern "C" void kernel_launch(void* const* d_in, const int* in_sizes, int n_in,
                              void* d_out, int out_size) {
    const float* q  = (const float*)d_in[0];
    const float* cp = (const float*)d_in[1];
    float* out      = (float*)d_out;

    cudaFuncSetAttribute(hyp_attn_kernel,
                         cudaFuncAttributeMaxDynamicSharedMemorySize, SMEM_BYTES);

    prep_kernel<<<NROWS / 8, 256>>>(q, cp);
    hyp_attn_kernel<<<NROWS / BM, 256, SMEM_BYTES>>>(cp, out);
}